// round 3
// baseline (speedup 1.0000x reference)
#include <cuda_runtime.h>
#include <math.h>

static constexpr int BATCH = 64;
static constexpr int H  = 256;
static constexpr int W  = 256;
static constexpr int HW = H * W;          // 65536
static constexpr int HW4 = HW / 4;        // 16384 float4 groups per channel
static constexpr int NK = 68;
static constexpr int GROUPS_PER_BLOCK = 512;   // 256 threads x 2 groups
static constexpr int CHUNKS = HW4 / GROUPS_PER_BLOCK;  // 32 blocks per batch

__device__ __forceinline__ float warp_sum(float v) {
    #pragma unroll
    for (int o = 16; o > 0; o >>= 1) v += __shfl_down_sync(0xffffffffu, v, o);
    return v;
}

// ---------------------------------------------------------------------------
// Fused kernel: every block redundantly solves its batch's Umeyama transform
// (gather 68 kpts -> reduce -> 3x3 fp32 Jacobi SVD on one thread), then
// applies it to its chunk of the 3x256x256 map. The serial solve latency
// overlaps across resident blocks; the kernel stays memory-bound.
// ---------------------------------------------------------------------------
__global__ void __launch_bounds__(256)
fused_kernel(const float* __restrict__ Off,
             const float* __restrict__ Pos,
             const float* __restrict__ Mp,
             const int*   __restrict__ uv,
             float*       __restrict__ Out)
{
    const int b    = blockIdx.y;
    const int tid  = threadIdx.x;
    const int wid  = tid >> 5;
    const int lane = tid & 31;

    __shared__ float part[10][8];
    __shared__ float ssum[10];
    __shared__ float smu[6];
    __shared__ float sP[12];

    // ---------------- gather keypoints ----------------
    float s0 = 0.f, s1 = 0.f, s2 = 0.f;
    float d0 = 0.f, d1 = 0.f, d2 = 0.f;
    if (tid < NK) {
        const int h = uv[2 * tid + 0];
        const int w = uv[2 * tid + 1];
        const int base = b * 3 * HW + h * W + w;
        const int mb   = h * W + w;
        // offsetmap = (Offset*4 + mean) * REVERT, REVERT = [1,-1,1]
        s0 =  fmaf(Off[base         ], 4.0f, Mp[mb         ]);
        s1 = -fmaf(Off[base +    HW ], 4.0f, Mp[mb +    HW ]);
        s2 =  fmaf(Off[base + 2*HW  ], 4.0f, Mp[mb + 2*HW  ]);
        d0 = Pos[base];
        d1 = Pos[base + HW];
        d2 = Pos[base + 2 * HW];
    }

    // ---------------- reduce coordinate sums -> means ----------------
    {
        float v0 = warp_sum(s0), v1 = warp_sum(s1), v2 = warp_sum(s2);
        float v3 = warp_sum(d0), v4 = warp_sum(d1), v5 = warp_sum(d2);
        if (lane == 0) {
            part[0][wid] = v0; part[1][wid] = v1; part[2][wid] = v2;
            part[3][wid] = v3; part[4][wid] = v4; part[5][wid] = v5;
        }
    }
    __syncthreads();
    if (tid < 6) {
        float t = 0.f;
        #pragma unroll
        for (int j = 0; j < 8; j++) t += part[tid][j];
        smu[tid] = t * (1.0f / NK);
    }
    __syncthreads();

    // ---------------- reduce A = dd^T sd / n and var_s ----------------
    {
        float a[9] = {0,0,0,0,0,0,0,0,0};
        float var  = 0.f;
        if (tid < NK) {
            const float c0 = s0 - smu[0], c1 = s1 - smu[1], c2 = s2 - smu[2];
            const float e0 = d0 - smu[3], e1 = d1 - smu[4], e2 = d2 - smu[5];
            a[0] = e0*c0; a[1] = e0*c1; a[2] = e0*c2;
            a[3] = e1*c0; a[4] = e1*c1; a[5] = e1*c2;
            a[6] = e2*c0; a[7] = e2*c1; a[8] = e2*c2;
            var  = c0*c0 + c1*c1 + c2*c2;
        }
        #pragma unroll
        for (int k = 0; k < 9; k++) {
            float v = warp_sum(a[k]);
            if (lane == 0) part[k][wid] = v;
        }
        float v = warp_sum(var);
        if (lane == 0) part[9][wid] = v;
    }
    __syncthreads();
    if (tid < 10) {
        float t = 0.f;
        #pragma unroll
        for (int j = 0; j < 8; j++) t += part[tid][j];
        ssum[tid] = t * (1.0f / NK);
    }
    __syncthreads();

    // ---------------- thread 0: fp32 3x3 SVD (Jacobi on A^T A) ----------------
    if (tid == 0) {
        float A[3][3];
        #pragma unroll
        for (int i = 0; i < 3; i++)
            #pragma unroll
            for (int j = 0; j < 3; j++)
                A[i][j] = ssum[i * 3 + j];
        const float var_s = ssum[9];

        const float detA =
              A[0][0] * (A[1][1] * A[2][2] - A[1][2] * A[2][1])
            - A[0][1] * (A[1][0] * A[2][2] - A[1][2] * A[2][0])
            + A[0][2] * (A[1][0] * A[2][1] - A[1][1] * A[2][0]);

        float Bm[3][3], Vm[3][3] = {{1,0,0},{0,1,0},{0,0,1}};
        #pragma unroll
        for (int i = 0; i < 3; i++)
            #pragma unroll
            for (int j = 0; j < 3; j++) {
                float acc = 0.0f;
                #pragma unroll
                for (int k = 0; k < 3; k++) acc += A[k][i] * A[k][j];
                Bm[i][j] = acc;
            }

        const int PP[3] = {0, 0, 1}, QQ[3] = {1, 2, 2};
        #pragma unroll 1
        for (int sweep = 0; sweep < 6; sweep++) {
            #pragma unroll
            for (int r = 0; r < 3; r++) {
                const int p = PP[r], q = QQ[r];
                const float apq = Bm[p][q];
                if (fabsf(apq) < 1e-30f) continue;
                const float theta = (Bm[q][q] - Bm[p][p]) / (2.0f * apq);
                const float tt = ((theta >= 0.0f) ? 1.0f : -1.0f) /
                                 (fabsf(theta) + sqrtf(theta * theta + 1.0f));
                const float c = rsqrtf(tt * tt + 1.0f);
                const float s = tt * c;
                #pragma unroll
                for (int k = 0; k < 3; k++) {
                    const float bkp = Bm[k][p], bkq = Bm[k][q];
                    Bm[k][p] = c * bkp - s * bkq;
                    Bm[k][q] = s * bkp + c * bkq;
                }
                #pragma unroll
                for (int k = 0; k < 3; k++) {
                    const float bpk = Bm[p][k], bqk = Bm[q][k];
                    Bm[p][k] = c * bpk - s * bqk;
                    Bm[q][k] = s * bpk + c * bqk;
                }
                #pragma unroll
                for (int k = 0; k < 3; k++) {
                    const float vkp = Vm[k][p], vkq = Vm[k][q];
                    Vm[k][p] = c * vkp - s * vkq;
                    Vm[k][q] = s * vkp + c * vkq;
                }
            }
        }

        float wv[3] = {Bm[0][0], Bm[1][1], Bm[2][2]};
        int id[3] = {0, 1, 2};
        if (wv[id[0]] < wv[id[1]]) { int t = id[0]; id[0] = id[1]; id[1] = t; }
        if (wv[id[1]] < wv[id[2]]) { int t = id[1]; id[1] = id[2]; id[2] = t; }
        if (wv[id[0]] < wv[id[1]]) { int t = id[0]; id[0] = id[1]; id[1] = t; }

        float U[3][3], Vc[3][3], sv[3];
        #pragma unroll
        for (int i = 0; i < 3; i++) {
            const int j = id[i];
            const float v0 = Vm[0][j], v1 = Vm[1][j], v2 = Vm[2][j];
            const float u0 = A[0][0]*v0 + A[0][1]*v1 + A[0][2]*v2;
            const float u1 = A[1][0]*v0 + A[1][1]*v1 + A[1][2]*v2;
            const float u2 = A[2][0]*v0 + A[2][1]*v1 + A[2][2]*v2;
            const float nu = sqrtf(u0*u0 + u1*u1 + u2*u2);  // sigma_i
            sv[i] = nu;
            const float inv = (nu > 1e-30f) ? 1.0f / nu : 0.0f;
            U[0][i] = u0 * inv; U[1][i] = u1 * inv; U[2][i] = u2 * inv;
            Vc[0][i] = v0; Vc[1][i] = v1; Vc[2][i] = v2;
        }

        const float d3 = (detA < 0.0f) ? -1.0f : 1.0f;
        const float dd[3] = {1.0f, 1.0f, d3};
        const float scale = (sv[0] + sv[1] + d3 * sv[2]) / var_s;

        #pragma unroll
        for (int r = 0; r < 3; r++) {
            float row[3];
            #pragma unroll
            for (int c = 0; c < 3; c++) {
                float acc = 0.0f;
                #pragma unroll
                for (int i = 0; i < 3; i++) acc += dd[i] * U[r][i] * Vc[c][i];
                row[c] = scale * acc;
                sP[r * 3 + c] = row[c];
            }
            sP[9 + r] = smu[3 + r]
                - (row[0] * smu[0] + row[1] * smu[1] + row[2] * smu[2]);
        }
    }
    __syncthreads();

    // ---------------- apply transform to this block's chunk ----------------
    const float p00 = sP[0], p01 = sP[1], p02 = sP[2];
    const float p10 = sP[3], p11 = sP[4], p12 = sP[5];
    const float p20 = sP[6], p21 = sP[7], p22 = sP[8];
    const float t0  = sP[9], t1  = sP[10], t2 = sP[11];

    const float4* Off4 = (const float4*)Off;
    const float4* Mp4  = (const float4*)Mp;
    float4*       Out4 = (float4*)Out;

    const int g0 = blockIdx.x * GROUPS_PER_BLOCK + tid;

    #pragma unroll
    for (int it = 0; it < 2; it++) {
        const int g    = g0 + it * 256;
        const int base = b * 3 * HW4 + g;

        const float4 o0 = Off4[base];
        const float4 o1 = Off4[base + HW4];
        const float4 o2 = Off4[base + 2 * HW4];
        const float4 m0 = Mp4[g];
        const float4 m1 = Mp4[g + HW4];
        const float4 m2 = Mp4[g + 2 * HW4];

        float4 r0, r1, r2;
#define APPLY_LANE(j)                                                        \
        {                                                                    \
            const float x =  fmaf(o0.j, 4.0f, m0.j);                         \
            const float y = -fmaf(o1.j, 4.0f, m1.j);                         \
            const float z =  fmaf(o2.j, 4.0f, m2.j);                         \
            r0.j = fmaf(p00, x, fmaf(p01, y, fmaf(p02, z, t0)));             \
            r1.j = fmaf(p10, x, fmaf(p11, y, fmaf(p12, z, t1)));             \
            r2.j = fmaf(p20, x, fmaf(p21, y, fmaf(p22, z, t2)));             \
        }
        APPLY_LANE(x)
        APPLY_LANE(y)
        APPLY_LANE(z)
        APPLY_LANE(w)
#undef APPLY_LANE

        Out4[base]           = r0;
        Out4[base + HW4]     = r1;
        Out4[base + 2 * HW4] = r2;
    }
}

// ---------------------------------------------------------------------------
extern "C" void kernel_launch(void* const* d_in, const int* in_sizes, int n_in,
                              void* d_out, int out_size)
{
    const float* Off = (const float*)d_in[0];   // [64,3,256,256]
    const float* Pos = (const float*)d_in[1];   // [64,3,256,256]
    const float* Mp  = (const float*)d_in[2];   // [3,256,256]
    const int*   uv  = (const int*)  d_in[3];   // [68,2]
    float*       Out = (float*)d_out;           // [64,3,256,256]

    dim3 grid(CHUNKS, BATCH);   // 32 x 64 = 2048 blocks
    fused_kernel<<<grid, 256>>>(Off, Pos, Mp, uv, Out);
}

// round 4
// speedup vs baseline: 1.7387x; 1.7387x over previous
#include <cuda_runtime.h>
#include <math.h>

static constexpr int BATCH = 64;
static constexpr int H  = 256;
static constexpr int W  = 256;
static constexpr int HW = H * W;          // 65536
static constexpr int HW4 = HW / 4;        // 16384 float4 groups per channel
static constexpr int NK = 68;

// Per-batch similarity transform: 9 floats sR (row-major [d][c]) + 3 floats t.
__device__ float g_params[BATCH * 12];

__device__ __forceinline__ float warp_sum(float v) {
    #pragma unroll
    for (int o = 16; o > 0; o >>= 1) v += __shfl_down_sync(0xffffffffu, v, o);
    return v;
}

// ---------------------------------------------------------------------------
// Kernel 1: per-batch Umeyama estimation (64 blocks x 128 threads).
// Single-pass raw-moment reduction (A = P/n - mu_d mu_s^T), warp shuffles,
// fp32 Jacobi SVD (5 sweeps) on thread 0.
// ---------------------------------------------------------------------------
__global__ void __launch_bounds__(128)
estimate_kernel(const float* __restrict__ Off,
                const float* __restrict__ Pos,
                const float* __restrict__ Mp,
                const int*   __restrict__ uv)
{
    const int b    = blockIdx.x;
    const int tid  = threadIdx.x;
    const int wid  = tid >> 5;
    const int lane = tid & 31;

    __shared__ float part[16][4];

    // ---- gather keypoint pair ----
    float s0 = 0.f, s1 = 0.f, s2 = 0.f;
    float d0 = 0.f, d1 = 0.f, d2 = 0.f;
    if (tid < NK) {
        const int h = __ldg(&uv[2 * tid + 0]);
        const int w = __ldg(&uv[2 * tid + 1]);
        const int base = b * 3 * HW + h * W + w;
        const int mb   = h * W + w;
        // offsetmap = (Offset*4 + mean) * REVERT, REVERT = [1,-1,1]
        s0 =  fmaf(Off[base         ], 4.0f, Mp[mb         ]);
        s1 = -fmaf(Off[base +    HW ], 4.0f, Mp[mb +    HW ]);
        s2 =  fmaf(Off[base + 2*HW  ], 4.0f, Mp[mb + 2*HW  ]);
        d0 = Pos[base];
        d1 = Pos[base + HW];
        d2 = Pos[base + 2 * HW];
    }

    // ---- 16 raw moments in one pass ----
    float m[16];
    m[0]  = s0;       m[1]  = s1;       m[2]  = s2;       // sum s
    m[3]  = d0;       m[4]  = d1;       m[5]  = d2;       // sum d
    m[6]  = d0 * s0;  m[7]  = d0 * s1;  m[8]  = d0 * s2;  // P = sum d s^T
    m[9]  = d1 * s0;  m[10] = d1 * s1;  m[11] = d1 * s2;
    m[12] = d2 * s0;  m[13] = d2 * s1;  m[14] = d2 * s2;
    m[15] = s0 * s0 + s1 * s1 + s2 * s2;                  // Q

    #pragma unroll
    for (int k = 0; k < 16; k++) {
        const float v = warp_sum(m[k]);
        if (lane == 0) part[k][wid] = v;
    }
    __syncthreads();

    if (tid == 0) {
        const float inv_n = 1.0f / NK;
        float S[16];
        #pragma unroll
        for (int k = 0; k < 16; k++)
            S[k] = (part[k][0] + part[k][1] + part[k][2] + part[k][3]) * inv_n;

        const float mus0 = S[0], mus1 = S[1], mus2 = S[2];
        const float mud0 = S[3], mud1 = S[4], mud2 = S[5];

        float A[3][3];
        A[0][0] = S[6]  - mud0 * mus0; A[0][1] = S[7]  - mud0 * mus1; A[0][2] = S[8]  - mud0 * mus2;
        A[1][0] = S[9]  - mud1 * mus0; A[1][1] = S[10] - mud1 * mus1; A[1][2] = S[11] - mud1 * mus2;
        A[2][0] = S[12] - mud2 * mus0; A[2][1] = S[13] - mud2 * mus1; A[2][2] = S[14] - mud2 * mus2;
        const float var_s = S[15] - (mus0*mus0 + mus1*mus1 + mus2*mus2);

        const float detA =
              A[0][0] * (A[1][1] * A[2][2] - A[1][2] * A[2][1])
            - A[0][1] * (A[1][0] * A[2][2] - A[1][2] * A[2][0])
            + A[0][2] * (A[1][0] * A[2][1] - A[1][1] * A[2][0]);

        // Bm = A^T A (symmetric PSD), Jacobi eigen -> V, then U from A V.
        float Bm[3][3], Vm[3][3] = {{1,0,0},{0,1,0},{0,0,1}};
        #pragma unroll
        for (int i = 0; i < 3; i++)
            #pragma unroll
            for (int j = 0; j < 3; j++) {
                float acc = 0.0f;
                #pragma unroll
                for (int k = 0; k < 3; k++) acc += A[k][i] * A[k][j];
                Bm[i][j] = acc;
            }

        const int PP[3] = {0, 0, 1}, QQ[3] = {1, 2, 2};
        #pragma unroll 1
        for (int sweep = 0; sweep < 5; sweep++) {
            #pragma unroll
            for (int r = 0; r < 3; r++) {
                const int p = PP[r], q = QQ[r];
                const float apq = Bm[p][q];
                if (fabsf(apq) < 1e-30f) continue;
                const float theta = (Bm[q][q] - Bm[p][p]) / (2.0f * apq);
                const float tt = ((theta >= 0.0f) ? 1.0f : -1.0f) /
                                 (fabsf(theta) + sqrtf(theta * theta + 1.0f));
                const float c = rsqrtf(tt * tt + 1.0f);
                const float s = tt * c;
                #pragma unroll
                for (int k = 0; k < 3; k++) {
                    const float bkp = Bm[k][p], bkq = Bm[k][q];
                    Bm[k][p] = c * bkp - s * bkq;
                    Bm[k][q] = s * bkp + c * bkq;
                }
                #pragma unroll
                for (int k = 0; k < 3; k++) {
                    const float bpk = Bm[p][k], bqk = Bm[q][k];
                    Bm[p][k] = c * bpk - s * bqk;
                    Bm[q][k] = s * bpk + c * bqk;
                }
                #pragma unroll
                for (int k = 0; k < 3; k++) {
                    const float vkp = Vm[k][p], vkq = Vm[k][q];
                    Vm[k][p] = c * vkp - s * vkq;
                    Vm[k][q] = s * vkp + c * vkq;
                }
            }
        }

        float wv[3] = {Bm[0][0], Bm[1][1], Bm[2][2]};
        int id[3] = {0, 1, 2};
        if (wv[id[0]] < wv[id[1]]) { int t = id[0]; id[0] = id[1]; id[1] = t; }
        if (wv[id[1]] < wv[id[2]]) { int t = id[1]; id[1] = id[2]; id[2] = t; }
        if (wv[id[0]] < wv[id[1]]) { int t = id[0]; id[0] = id[1]; id[1] = t; }

        float U[3][3], Vc[3][3], sv[3];
        #pragma unroll
        for (int i = 0; i < 3; i++) {
            const int j = id[i];
            const float v0 = Vm[0][j], v1 = Vm[1][j], v2 = Vm[2][j];
            const float u0 = A[0][0]*v0 + A[0][1]*v1 + A[0][2]*v2;
            const float u1 = A[1][0]*v0 + A[1][1]*v1 + A[1][2]*v2;
            const float u2 = A[2][0]*v0 + A[2][1]*v1 + A[2][2]*v2;
            const float nu = sqrtf(u0*u0 + u1*u1 + u2*u2);  // sigma_i
            sv[i] = nu;
            const float inv = (nu > 1e-30f) ? 1.0f / nu : 0.0f;
            U[0][i] = u0 * inv; U[1][i] = u1 * inv; U[2][i] = u2 * inv;
            Vc[0][i] = v0; Vc[1][i] = v1; Vc[2][i] = v2;
        }

        const float d3 = (detA < 0.0f) ? -1.0f : 1.0f;
        const float dd[3] = {1.0f, 1.0f, d3};
        const float scale = (sv[0] + sv[1] + d3 * sv[2]) / var_s;

        float* outp = g_params + b * 12;
        #pragma unroll
        for (int r = 0; r < 3; r++) {
            float row[3];
            #pragma unroll
            for (int c = 0; c < 3; c++) {
                float acc = 0.0f;
                #pragma unroll
                for (int i = 0; i < 3; i++) acc += dd[i] * U[r][i] * Vc[c][i];
                row[c] = scale * acc;
                outp[r * 3 + c] = row[c];
            }
            outp[9 + r] = ((r == 0) ? mud0 : (r == 1) ? mud1 : mud2)
                - (row[0] * mus0 + row[1] * mus1 + row[2] * mus2);
        }
    }
}

// ---------------------------------------------------------------------------
// Kernel 2: apply transform to the full 64x3x256x256 map (HBM-bound, float4).
// Default cache policy — the working set partially lives in L2 across replays
// and streaming hints were measured to cost +0.8us.
// ---------------------------------------------------------------------------
__global__ void __launch_bounds__(256)
apply_kernel(const float4* __restrict__ Off,
             const float4* __restrict__ Mp,
             float4*       __restrict__ Out)
{
    const int idx = blockIdx.x * blockDim.x + threadIdx.x;  // 64*16384 threads
    const int b = idx >> 14;            // 16384 float4 groups per batch image
    const int g = idx & 16383;

    const float* p = g_params + b * 12; // uniform per block -> broadcast loads
    const float p00 = p[0], p01 = p[1], p02 = p[2];
    const float p10 = p[3], p11 = p[4], p12 = p[5];
    const float p20 = p[6], p21 = p[7], p22 = p[8];
    const float t0  = p[9], t1  = p[10], t2 = p[11];

    const int base = b * 3 * HW4 + g;
    const float4 o0 = Off[base];
    const float4 o1 = Off[base + HW4];
    const float4 o2 = Off[base + 2 * HW4];
    const float4 m0 = Mp[g];
    const float4 m1 = Mp[g + HW4];
    const float4 m2 = Mp[g + 2 * HW4];

    float4 r0, r1, r2;

#define APPLY_LANE(j)                                                        \
    {                                                                        \
        const float x =  fmaf(o0.j, 4.0f, m0.j);                             \
        const float y = -fmaf(o1.j, 4.0f, m1.j);                             \
        const float z =  fmaf(o2.j, 4.0f, m2.j);                             \
        r0.j = fmaf(p00, x, fmaf(p01, y, fmaf(p02, z, t0)));                 \
        r1.j = fmaf(p10, x, fmaf(p11, y, fmaf(p12, z, t1)));                 \
        r2.j = fmaf(p20, x, fmaf(p21, y, fmaf(p22, z, t2)));                 \
    }

    APPLY_LANE(x)
    APPLY_LANE(y)
    APPLY_LANE(z)
    APPLY_LANE(w)
#undef APPLY_LANE

    Out[base]           = r0;
    Out[base + HW4]     = r1;
    Out[base + 2 * HW4] = r2;
}

// ---------------------------------------------------------------------------
extern "C" void kernel_launch(void* const* d_in, const int* in_sizes, int n_in,
                              void* d_out, int out_size)
{
    const float* Off = (const float*)d_in[0];   // [64,3,256,256]
    const float* Pos = (const float*)d_in[1];   // [64,3,256,256]
    const float* Mp  = (const float*)d_in[2];   // [3,256,256]
    const int*   uv  = (const int*)  d_in[3];   // [68,2]
    float*       Out = (float*)d_out;           // [64,3,256,256]

    estimate_kernel<<<BATCH, 128>>>(Off, Pos, Mp, uv);

    const int total4 = BATCH * HW4;             // 1,048,576 threads
    apply_kernel<<<total4 / 256, 256>>>((const float4*)Off,
                                        (const float4*)Mp,
                                        (float4*)Out);
}

// round 7
// speedup vs baseline: 1.7477x; 1.0052x over previous
#include <cuda_runtime.h>
#include <math.h>

static constexpr int BATCH = 64;
static constexpr int H  = 256;
static constexpr int W  = 256;
static constexpr int HW = H * W;          // 65536
static constexpr int HW4 = HW / 4;        // 16384 float4 groups per channel
static constexpr int NK = 68;

// Per-batch similarity transform: 9 floats sR (row-major [d][c]) + 3 floats t.
__device__ float g_params[BATCH * 12];

__device__ __forceinline__ float warp_sum(float v) {
    #pragma unroll
    for (int o = 16; o > 0; o >>= 1) v += __shfl_down_sync(0xffffffffu, v, o);
    return v;
}

// ---------------------------------------------------------------------------
// Kernel 1: per-batch Umeyama estimation (64 blocks x 128 threads).
// Single-pass raw-moment reduction, warp shuffles, fp32 Jacobi SVD (5 sweeps).
// ---------------------------------------------------------------------------
__global__ void __launch_bounds__(128)
estimate_kernel(const float* __restrict__ Off,
                const float* __restrict__ Pos,
                const float* __restrict__ Mp,
                const int*   __restrict__ uv)
{
    const int b    = blockIdx.x;
    const int tid  = threadIdx.x;
    const int wid  = tid >> 5;
    const int lane = tid & 31;

    __shared__ float part[16][4];

    // ---- gather keypoint pair ----
    float s0 = 0.f, s1 = 0.f, s2 = 0.f;
    float d0 = 0.f, d1 = 0.f, d2 = 0.f;
    if (tid < NK) {
        const int h = __ldg(&uv[2 * tid + 0]);
        const int w = __ldg(&uv[2 * tid + 1]);
        const int base = b * 3 * HW + h * W + w;
        const int mb   = h * W + w;
        // offsetmap = (Offset*4 + mean) * REVERT, REVERT = [1,-1,1]
        s0 =  fmaf(Off[base         ], 4.0f, Mp[mb         ]);
        s1 = -fmaf(Off[base +    HW ], 4.0f, Mp[mb +    HW ]);
        s2 =  fmaf(Off[base + 2*HW  ], 4.0f, Mp[mb + 2*HW  ]);
        d0 = Pos[base];
        d1 = Pos[base + HW];
        d2 = Pos[base + 2 * HW];
    }

    // ---- 16 raw moments in one pass ----
    float m[16];
    m[0]  = s0;       m[1]  = s1;       m[2]  = s2;       // sum s
    m[3]  = d0;       m[4]  = d1;       m[5]  = d2;       // sum d
    m[6]  = d0 * s0;  m[7]  = d0 * s1;  m[8]  = d0 * s2;  // P = sum d s^T
    m[9]  = d1 * s0;  m[10] = d1 * s1;  m[11] = d1 * s2;
    m[12] = d2 * s0;  m[13] = d2 * s1;  m[14] = d2 * s2;
    m[15] = s0 * s0 + s1 * s1 + s2 * s2;                  // Q

    #pragma unroll
    for (int k = 0; k < 16; k++) {
        const float v = warp_sum(m[k]);
        if (lane == 0) part[k][wid] = v;
    }
    __syncthreads();

    if (tid == 0) {
        const float inv_n = 1.0f / NK;
        float S[16];
        #pragma unroll
        for (int k = 0; k < 16; k++)
            S[k] = (part[k][0] + part[k][1] + part[k][2] + part[k][3]) * inv_n;

        const float mus0 = S[0], mus1 = S[1], mus2 = S[2];
        const float mud0 = S[3], mud1 = S[4], mud2 = S[5];

        float A[3][3];
        A[0][0] = S[6]  - mud0 * mus0; A[0][1] = S[7]  - mud0 * mus1; A[0][2] = S[8]  - mud0 * mus2;
        A[1][0] = S[9]  - mud1 * mus0; A[1][1] = S[10] - mud1 * mus1; A[1][2] = S[11] - mud1 * mus2;
        A[2][0] = S[12] - mud2 * mus0; A[2][1] = S[13] - mud2 * mus1; A[2][2] = S[14] - mud2 * mus2;
        const float var_s = S[15] - (mus0*mus0 + mus1*mus1 + mus2*mus2);

        const float detA =
              A[0][0] * (A[1][1] * A[2][2] - A[1][2] * A[2][1])
            - A[0][1] * (A[1][0] * A[2][2] - A[1][2] * A[2][0])
            + A[0][2] * (A[1][0] * A[2][1] - A[1][1] * A[2][0]);

        float Bm[3][3], Vm[3][3] = {{1,0,0},{0,1,0},{0,0,1}};
        #pragma unroll
        for (int i = 0; i < 3; i++)
            #pragma unroll
            for (int j = 0; j < 3; j++) {
                float acc = 0.0f;
                #pragma unroll
                for (int k = 0; k < 3; k++) acc += A[k][i] * A[k][j];
                Bm[i][j] = acc;
            }

        const int PP[3] = {0, 0, 1}, QQ[3] = {1, 2, 2};
        #pragma unroll 1
        for (int sweep = 0; sweep < 5; sweep++) {
            #pragma unroll
            for (int r = 0; r < 3; r++) {
                const int p = PP[r], q = QQ[r];
                const float apq = Bm[p][q];
                if (fabsf(apq) < 1e-30f) continue;
                const float theta = (Bm[q][q] - Bm[p][p]) / (2.0f * apq);
                const float tt = ((theta >= 0.0f) ? 1.0f : -1.0f) /
                                 (fabsf(theta) + sqrtf(theta * theta + 1.0f));
                const float c = rsqrtf(tt * tt + 1.0f);
                const float s = tt * c;
                #pragma unroll
                for (int k = 0; k < 3; k++) {
                    const float bkp = Bm[k][p], bkq = Bm[k][q];
                    Bm[k][p] = c * bkp - s * bkq;
                    Bm[k][q] = s * bkp + c * bkq;
                }
                #pragma unroll
                for (int k = 0; k < 3; k++) {
                    const float bpk = Bm[p][k], bqk = Bm[q][k];
                    Bm[p][k] = c * bpk - s * bqk;
                    Bm[q][k] = s * bpk + c * bqk;
                }
                #pragma unroll
                for (int k = 0; k < 3; k++) {
                    const float vkp = Vm[k][p], vkq = Vm[k][q];
                    Vm[k][p] = c * vkp - s * vkq;
                    Vm[k][q] = s * vkp + c * vkq;
                }
            }
        }

        float wv[3] = {Bm[0][0], Bm[1][1], Bm[2][2]};
        int id[3] = {0, 1, 2};
        if (wv[id[0]] < wv[id[1]]) { int t = id[0]; id[0] = id[1]; id[1] = t; }
        if (wv[id[1]] < wv[id[2]]) { int t = id[1]; id[1] = id[2]; id[2] = t; }
        if (wv[id[0]] < wv[id[1]]) { int t = id[0]; id[0] = id[1]; id[1] = t; }

        float U[3][3], Vc[3][3], sv[3];
        #pragma unroll
        for (int i = 0; i < 3; i++) {
            const int j = id[i];
            const float v0 = Vm[0][j], v1 = Vm[1][j], v2 = Vm[2][j];
            const float u0 = A[0][0]*v0 + A[0][1]*v1 + A[0][2]*v2;
            const float u1 = A[1][0]*v0 + A[1][1]*v1 + A[1][2]*v2;
            const float u2 = A[2][0]*v0 + A[2][1]*v1 + A[2][2]*v2;
            const float nu = sqrtf(u0*u0 + u1*u1 + u2*u2);  // sigma_i
            sv[i] = nu;
            const float inv = (nu > 1e-30f) ? 1.0f / nu : 0.0f;
            U[0][i] = u0 * inv; U[1][i] = u1 * inv; U[2][i] = u2 * inv;
            Vc[0][i] = v0; Vc[1][i] = v1; Vc[2][i] = v2;
        }

        const float d3 = (detA < 0.0f) ? -1.0f : 1.0f;
        const float dd[3] = {1.0f, 1.0f, d3};
        const float scale = (sv[0] + sv[1] + d3 * sv[2]) / var_s;

        float* outp = g_params + b * 12;
        #pragma unroll
        for (int r = 0; r < 3; r++) {
            float row[3];
            #pragma unroll
            for (int c = 0; c < 3; c++) {
                float acc = 0.0f;
                #pragma unroll
                for (int i = 0; i < 3; i++) acc += dd[i] * U[r][i] * Vc[c][i];
                row[c] = scale * acc;
                outp[r * 3 + c] = row[c];
            }
            outp[9 + r] = ((r == 0) ? mud0 : (r == 1) ? mud1 : mud2)
                - (row[0] * mus0 + row[1] * mus1 + row[2] * mus2);
        }
    }
}

// ---------------------------------------------------------------------------
// Kernel 2: apply transform (HBM-bound, float4) with PDL overlap.
// Loads are issued BEFORE cudaGridDependencySynchronize so the memory stream
// starts while estimate_kernel is still finishing.
// ---------------------------------------------------------------------------
__global__ void __launch_bounds__(256)
apply_kernel(const float4* __restrict__ Off,
             const float4* __restrict__ Mp,
             float4*       __restrict__ Out)
{
    const int idx = blockIdx.x * blockDim.x + threadIdx.x;  // 64*16384 threads
    const int b = idx >> 14;            // 16384 float4 groups per batch image
    const int g = idx & 16383;

    const int base = b * 3 * HW4 + g;

    // Independent work first: pull the bulk data (does not depend on primary).
    const float4 o0 = Off[base];
    const float4 o1 = Off[base + HW4];
    const float4 o2 = Off[base + 2 * HW4];
    const float4 m0 = Mp[g];
    const float4 m1 = Mp[g + HW4];
    const float4 m2 = Mp[g + 2 * HW4];

    // Now wait for estimate_kernel's g_params writes to be visible.
#if __CUDA_ARCH__ >= 900
    cudaGridDependencySynchronize();
#endif

    const float* p = g_params + b * 12; // uniform per block -> broadcast loads
    const float p00 = p[0], p01 = p[1], p02 = p[2];
    const float p10 = p[3], p11 = p[4], p12 = p[5];
    const float p20 = p[6], p21 = p[7], p22 = p[8];
    const float t0  = p[9], t1  = p[10], t2 = p[11];

    float4 r0, r1, r2;

#define APPLY_LANE(j)                                                        \
    {                                                                        \
        const float x =  fmaf(o0.j, 4.0f, m0.j);                             \
        const float y = -fmaf(o1.j, 4.0f, m1.j);                             \
        const float z =  fmaf(o2.j, 4.0f, m2.j);                             \
        r0.j = fmaf(p00, x, fmaf(p01, y, fmaf(p02, z, t0)));                 \
        r1.j = fmaf(p10, x, fmaf(p11, y, fmaf(p12, z, t1)));                 \
        r2.j = fmaf(p20, x, fmaf(p21, y, fmaf(p22, z, t2)));                 \
    }

    APPLY_LANE(x)
    APPLY_LANE(y)
    APPLY_LANE(z)
    APPLY_LANE(w)
#undef APPLY_LANE

    Out[base]           = r0;
    Out[base + HW4]     = r1;
    Out[base + 2 * HW4] = r2;
}

// ---------------------------------------------------------------------------
extern "C" void kernel_launch(void* const* d_in, const int* in_sizes, int n_in,
                              void* d_out, int out_size)
{
    const float* Off = (const float*)d_in[0];   // [64,3,256,256]
    const float* Pos = (const float*)d_in[1];   // [64,3,256,256]
    const float* Mp  = (const float*)d_in[2];   // [3,256,256]
    const int*   uv  = (const int*)  d_in[3];   // [68,2]
    float*       Out = (float*)d_out;           // [64,3,256,256]

    estimate_kernel<<<BATCH, 128>>>(Off, Pos, Mp, uv);

    // Launch apply with Programmatic Stream Serialization so it overlaps the
    // tail of estimate_kernel; apply waits via cudaGridDependencySynchronize.
    // Stream handle 0 here resolves to the SAME default-stream semantics as
    // the <<<>>> launch above in this TU (explicit cudaStreamLegacy broke
    // graph capture in R6 — do not reintroduce it).
    const int total4 = BATCH * HW4;             // 1,048,576 threads
    cudaLaunchConfig_t cfg = {};
    cfg.gridDim  = dim3(total4 / 256, 1, 1);
    cfg.blockDim = dim3(256, 1, 1);
    cfg.dynamicSmemBytes = 0;
    cfg.stream = 0;
    cudaLaunchAttribute attr[1];
    attr[0].id = cudaLaunchAttributeProgrammaticStreamSerialization;
    attr[0].val.programmaticStreamSerializationAllowed = 1;
    cfg.attrs = attr;
    cfg.numAttrs = 1;
    cudaLaunchKernelEx(&cfg, apply_kernel,
                       (const float4*)Off, (const float4*)Mp, (float4*)Out);
}